// round 1
// baseline (speedup 1.0000x reference)
#include <cuda_runtime.h>

#define MAXN 50176
#define HD 64

// Scratch (no allocation allowed -> __device__ globals), 16B-aligned for float4/red.v4
__device__ __align__(256) float g_h[MAXN * HD];    // transformed features of current layer
__device__ __align__(256) float g_x[MAXN * HD];    // layer input (output of previous layer)
__device__ __align__(256) float g_acc[MAXN * HD];  // unnormalized weighted sums
__device__ __align__(256) float g_s[MAXN];
__device__ __align__(256) float g_d[MAXN];
__device__ __align__(256) float g_m[MAXN];
__device__ __align__(256) float g_den[MAXN];

__device__ __forceinline__ float leaky(float v) { return v > 0.f ? v : 0.2f * v; }

__device__ __forceinline__ void atomicMaxF(float* addr, float v) {
    if (v >= 0.f) atomicMax((int*)addr, __float_as_int(v));
    else          atomicMin((unsigned int*)addr, __float_as_uint(v));
}

// ---------------- Layer 1 transform: x [N,1] @ W1 [1,64] ----------------
__global__ void transform1(const float* __restrict__ x, const float* __restrict__ W1,
                           const float* __restrict__ as1, const float* __restrict__ ad1, int N) {
    int idx = blockIdx.x * blockDim.x + threadIdx.x;
    if (idx >= N * 16) return;
    int i = idx >> 4, q = idx & 15;
    float xv = x[i];
    float4 w = ((const float4*)W1)[q];
    ((float4*)g_h)[i * 16 + q] = make_float4(xv * w.x, xv * w.y, xv * w.z, xv * w.w);
    ((float4*)g_acc)[i * 16 + q] = make_float4(0.f, 0.f, 0.f, 0.f);
    if (q == 0) {
        float cs = 0.f, cd = 0.f;
#pragma unroll
        for (int j = 0; j < 64; j++) { cs += W1[j] * as1[j]; cd += W1[j] * ad1[j]; }
        g_s[i] = xv * cs;
        g_d[i] = xv * cd;
        g_m[i] = __int_as_float(0xff800000);  // -inf
        g_den[i] = 0.f;
    }
}

// ---------------- 64x64 transform, warp per node ----------------
__global__ void transform2(const float* __restrict__ W, const float* __restrict__ as_,
                           const float* __restrict__ ad_, int N) {
    int warp = (blockIdx.x * blockDim.x + threadIdx.x) >> 5;
    int lane = threadIdx.x & 31;
    if (warp >= N) return;
    const float* xin = g_x + warp * 64;
    float r0 = xin[lane], r1 = xin[lane + 32];
    float o0 = 0.f, o1 = 0.f;
#pragma unroll
    for (int k = 0; k < 64; k++) {
        float xk = __shfl_sync(0xffffffffu, (k < 32) ? r0 : r1, k & 31);
        o0 += xk * W[k * 64 + lane];
        o1 += xk * W[k * 64 + lane + 32];
    }
    g_h[warp * 64 + lane] = o0;
    g_h[warp * 64 + lane + 32] = o1;
    g_acc[warp * 64 + lane] = 0.f;
    g_acc[warp * 64 + lane + 32] = 0.f;
    float ps = o0 * as_[lane] + o1 * as_[lane + 32];
    float pd = o0 * ad_[lane] + o1 * ad_[lane + 32];
#pragma unroll
    for (int off = 16; off; off >>= 1) {
        ps += __shfl_down_sync(0xffffffffu, ps, off);
        pd += __shfl_down_sync(0xffffffffu, pd, off);
    }
    if (lane == 0) {
        g_s[warp] = ps;
        g_d[warp] = pd;
        g_m[warp] = __int_as_float(0xff800000);
        g_den[warp] = 0.f;
    }
}

// ---------------- Layer 3 transform: [64]->scalar, warp per node ----------------
__global__ void transform3(const float* __restrict__ W3, const float* __restrict__ as3,
                           const float* __restrict__ ad3, int N) {
    int warp = (blockIdx.x * blockDim.x + threadIdx.x) >> 5;
    int lane = threadIdx.x & 31;
    if (warp >= N) return;
    const float* xin = g_x + warp * 64;
    float p = xin[lane] * W3[lane] + xin[lane + 32] * W3[lane + 32];
#pragma unroll
    for (int off = 16; off; off >>= 1) p += __shfl_down_sync(0xffffffffu, p, off);
    if (lane == 0) {
        g_h[warp] = p;
        g_s[warp] = p * as3[0];
        g_d[warp] = p * ad3[0];
        g_m[warp] = __int_as_float(0xff800000);
        g_den[warp] = 0.f;
        g_acc[warp] = 0.f;
    }
}

// ---------------- Edge pass 1: segment max over dst ----------------
__global__ void edge_max(const int* __restrict__ src, const int* __restrict__ dst, int E, int Etot) {
    int e = blockIdx.x * blockDim.x + threadIdx.x;
    if (e >= Etot) return;
    int s, d;
    if (e < E) { s = src[e]; d = dst[e]; } else { s = d = e - E; }
    float v = leaky(g_s[s] + g_d[d]);
    atomicMaxF(&g_m[d], v);
}

// ---------------- Edge pass 2 (H=64): 16 lanes per edge, vector red atomics ----------------
__global__ void edge_accum64(const int* __restrict__ src, const int* __restrict__ dst, int E, int Etot) {
    int gid = blockIdx.x * blockDim.x + threadIdx.x;
    int e = gid >> 4;
    int lane = threadIdx.x & 31;
    int sub = lane & 15;
    int base = lane & 16;  // leader lane of this 16-group within the warp
    bool valid = (e < Etot);
    int s = 0, d = 0;
    float ex = 0.f;
    if (sub == 0 && valid) {
        if (e < E) { s = src[e]; d = dst[e]; } else { s = d = e - E; }
        float v = leaky(g_s[s] + g_d[d]);
        ex = exp2f((v - g_m[d]) * 1.4426950408889634f);
        atomicAdd(&g_den[d], ex);
    }
    s = __shfl_sync(0xffffffffu, s, base);
    d = __shfl_sync(0xffffffffu, d, base);
    ex = __shfl_sync(0xffffffffu, ex, base);
    // invalid groups: s=d=0, ex=0 -> harmless +0 into acc[0..63]
    float4 hv = ((const float4*)g_h)[s * 16 + sub];
    float cx = ex * hv.x, cy = ex * hv.y, cz = ex * hv.z, cw = ex * hv.w;
    float* p = g_acc + d * 64 + sub * 4;
    asm volatile("red.global.add.v4.f32 [%0], {%1, %2, %3, %4};"
                 :: "l"(p), "f"(cx), "f"(cy), "f"(cz), "f"(cw) : "memory");
}

// ---------------- Edge pass 2 (H=1, layer 3) ----------------
__global__ void edge_accum1(const int* __restrict__ src, const int* __restrict__ dst, int E, int Etot) {
    int e = blockIdx.x * blockDim.x + threadIdx.x;
    if (e >= Etot) return;
    int s, d;
    if (e < E) { s = src[e]; d = dst[e]; } else { s = d = e - E; }
    float v = leaky(g_s[s] + g_d[d]);
    float ex = exp2f((v - g_m[d]) * 1.4426950408889634f);
    atomicAdd(&g_den[d], ex);
    atomicAdd(&g_acc[d], ex * g_h[s]);
}

// ---------------- Finalize (H=64): out = relu(acc/den + b) -> g_x ----------------
__global__ void finalize64(const float* __restrict__ b, int N) {
    int idx = blockIdx.x * blockDim.x + threadIdx.x;
    if (idx >= N * 16) return;
    int i = idx >> 4, q = idx & 15;
    float4 a = ((const float4*)g_acc)[i * 16 + q];
    float inv = 1.f / g_den[i];
    float4 bb = ((const float4*)b)[q];
    float4 o;
    o.x = fmaxf(a.x * inv + bb.x, 0.f);
    o.y = fmaxf(a.y * inv + bb.y, 0.f);
    o.z = fmaxf(a.z * inv + bb.z, 0.f);
    o.w = fmaxf(a.w * inv + bb.w, 0.f);
    ((float4*)g_x)[i * 16 + q] = o;
}

// ---------------- Final output (layer 3, no relu) ----------------
__global__ void finalize_out(const float* __restrict__ b3, float* __restrict__ out, int N) {
    int i = blockIdx.x * blockDim.x + threadIdx.x;
    if (i >= N) return;
    out[i] = g_acc[i] / g_den[i] + b3[0];
}

extern "C" void kernel_launch(void* const* d_in, const int* in_sizes, int n_in,
                              void* d_out, int out_size) {
    const float* x   = (const float*)d_in[0];
    const int*   ei  = (const int*)d_in[1];
    // d_in[2] = edge_attr (unused)
    const float* W1  = (const float*)d_in[3];
    const float* as1 = (const float*)d_in[4];
    const float* ad1 = (const float*)d_in[5];
    const float* b1  = (const float*)d_in[6];
    const float* W2  = (const float*)d_in[7];
    const float* as2 = (const float*)d_in[8];
    const float* ad2 = (const float*)d_in[9];
    const float* b2  = (const float*)d_in[10];
    const float* W3  = (const float*)d_in[11];
    const float* as3 = (const float*)d_in[12];
    const float* ad3 = (const float*)d_in[13];
    const float* b3  = (const float*)d_in[14];

    int N = in_sizes[0];       // x is [N,1]
    int E = in_sizes[1] / 2;   // edge_index is [2,E]
    const int* src = ei;
    const int* dst = ei + E;
    int Etot = E + N;

    const int TB = 256;
    int gN16  = (N * 16 + TB - 1) / TB;
    int gN32  = (N * 32 + TB - 1) / TB;
    int gE    = (Etot + TB - 1) / TB;
    long long eaT = (long long)Etot * 16;
    int gEA   = (int)((eaT + TB - 1) / TB);
    int gN    = (N + TB - 1) / TB;

    // ---- Layer 1 ----
    transform1<<<gN16, TB>>>(x, W1, as1, ad1, N);
    edge_max<<<gE, TB>>>(src, dst, E, Etot);
    edge_accum64<<<gEA, TB>>>(src, dst, E, Etot);
    finalize64<<<gN16, TB>>>(b1, N);

    // ---- Layer 2 ----
    transform2<<<gN32, TB>>>(W2, as2, ad2, N);
    edge_max<<<gE, TB>>>(src, dst, E, Etot);
    edge_accum64<<<gEA, TB>>>(src, dst, E, Etot);
    finalize64<<<gN16, TB>>>(b2, N);

    // ---- Layer 3 ----
    transform3<<<gN32, TB>>>(W3, as3, ad3, N);
    edge_max<<<gE, TB>>>(src, dst, E, Etot);
    edge_accum1<<<gE, TB>>>(src, dst, E, Etot);
    finalize_out<<<gN, TB>>>(b3, (float*)d_out, N);
}

// round 2
// speedup vs baseline: 1.6645x; 1.6645x over previous
#include <cuda_runtime.h>

#define MAXN 50176
#define MAXE 1700000
#define LOG2E 1.4426950408889634f

// Scratch (__device__ globals; no allocation allowed)
__device__ __align__(256) float g_h[MAXN * 64];   // transformed features (current layer)
__device__ __align__(256) float g_x[MAXN * 64];   // layer input / output buffer
__device__ float g_s[MAXN];
__device__ float g_d[MAXN];
__device__ int g_deg[MAXN];
__device__ int g_offs[MAXN + 1];
__device__ int g_loc[MAXN];       // block-local exclusive scan
__device__ int g_cursor[MAXN];
__device__ int g_csr[MAXE];       // src indices grouped by dst
__device__ int g_bsums[256];

__device__ __forceinline__ float leaky(float v) { return v > 0.f ? v : 0.2f * v; }

// ======================= CSR build =======================
__global__ void deg_zero(int N) {
    int i = blockIdx.x * blockDim.x + threadIdx.x;
    if (i < N) g_deg[i] = 0;
}

__global__ void deg_hist(const int* __restrict__ dst, int E) {
    int e = blockIdx.x * blockDim.x + threadIdx.x;
    if (e < E) atomicAdd(&g_deg[dst[e]], 1);
}

// Block-level exclusive scan (256/block); writes block totals.
__global__ void scanA(int N) {
    __shared__ int sm[256];
    int t = threadIdx.x;
    int i = blockIdx.x * 256 + t;
    int v = (i < N) ? g_deg[i] : 0;
    sm[t] = v;
    __syncthreads();
#pragma unroll
    for (int o = 1; o < 256; o <<= 1) {
        int x = (t >= o) ? sm[t - o] : 0;
        __syncthreads();
        sm[t] += x;
        __syncthreads();
    }
    if (i < N) g_loc[i] = sm[t] - v;   // exclusive within block
    if (t == 255) g_bsums[blockIdx.x] = sm[255];
}

// Single block: exclusive scan of (<=256) block sums in place.
__global__ void scanB(int nb) {
    __shared__ int sm[256];
    int t = threadIdx.x;
    int v = (t < nb) ? g_bsums[t] : 0;
    sm[t] = v;
    __syncthreads();
#pragma unroll
    for (int o = 1; o < 256; o <<= 1) {
        int x = (t >= o) ? sm[t - o] : 0;
        __syncthreads();
        sm[t] += x;
        __syncthreads();
    }
    if (t < nb) g_bsums[t] = sm[t] - v;  // exclusive
}

__global__ void scanC(int N) {
    int i = blockIdx.x * blockDim.x + threadIdx.x;
    if (i >= N) return;
    int off = g_loc[i] + g_bsums[i >> 8];
    g_offs[i] = off;
    g_cursor[i] = off;
    if (i == N - 1) g_offs[N] = off + g_deg[i];
}

__global__ void scatter(const int* __restrict__ src, const int* __restrict__ dst, int E) {
    int e = blockIdx.x * blockDim.x + threadIdx.x;
    if (e >= E) return;
    int d = dst[e];
    int pos = atomicAdd(&g_cursor[d], 1);
    g_csr[pos] = src[e];
}

// ======================= Node transforms =======================
// Layer 1: x [N,1] @ W1 [1,64]
__global__ void transform1(const float* __restrict__ x, const float* __restrict__ W1,
                           const float* __restrict__ as1, const float* __restrict__ ad1, int N) {
    int idx = blockIdx.x * blockDim.x + threadIdx.x;
    if (idx >= N * 16) return;
    int i = idx >> 4, q = idx & 15;
    float xv = x[i];
    float4 w = ((const float4*)W1)[q];
    ((float4*)g_h)[i * 16 + q] = make_float4(xv * w.x, xv * w.y, xv * w.z, xv * w.w);
    if (q == 0) {
        float cs = 0.f, cd = 0.f;
#pragma unroll
        for (int j = 0; j < 64; j++) { cs += W1[j] * as1[j]; cd += W1[j] * ad1[j]; }
        g_s[i] = xv * cs;
        g_d[i] = xv * cd;
    }
}

// 64x64 transform, warp per node (layer 2)
__global__ void transform2(const float* __restrict__ W, const float* __restrict__ as_,
                           const float* __restrict__ ad_, int N) {
    int warp = (blockIdx.x * blockDim.x + threadIdx.x) >> 5;
    int lane = threadIdx.x & 31;
    if (warp >= N) return;
    const float* xin = g_x + warp * 64;
    float r0 = xin[lane], r1 = xin[lane + 32];
    float o0 = 0.f, o1 = 0.f;
#pragma unroll
    for (int k = 0; k < 64; k++) {
        float xk = __shfl_sync(0xffffffffu, (k < 32) ? r0 : r1, k & 31);
        o0 += xk * W[k * 64 + lane];
        o1 += xk * W[k * 64 + lane + 32];
    }
    g_h[warp * 64 + lane] = o0;
    g_h[warp * 64 + lane + 32] = o1;
    float ps = o0 * as_[lane] + o1 * as_[lane + 32];
    float pd = o0 * ad_[lane] + o1 * ad_[lane + 32];
#pragma unroll
    for (int off = 16; off; off >>= 1) {
        ps += __shfl_down_sync(0xffffffffu, ps, off);
        pd += __shfl_down_sync(0xffffffffu, pd, off);
    }
    if (lane == 0) { g_s[warp] = ps; g_d[warp] = pd; }
}

// Layer 3: [64] -> scalar, warp per node
__global__ void transform3(const float* __restrict__ W3, const float* __restrict__ as3,
                           const float* __restrict__ ad3, int N) {
    int warp = (blockIdx.x * blockDim.x + threadIdx.x) >> 5;
    int lane = threadIdx.x & 31;
    if (warp >= N) return;
    const float* xin = g_x + warp * 64;
    float p = xin[lane] * W3[lane] + xin[lane + 32] * W3[lane + 32];
#pragma unroll
    for (int off = 16; off; off >>= 1) p += __shfl_down_sync(0xffffffffu, p, off);
    if (lane == 0) {
        g_h[warp] = p;
        g_s[warp] = p * as3[0];
        g_d[warp] = p * ad3[0];
    }
}

// ======================= Fused GAT aggregation =======================
// H=64, warp per dst node: max -> softmax-weighted gather -> write relu(out).
template <bool RELU>
__global__ void gat64(const float* __restrict__ b, int N) {
    int node = (blockIdx.x * blockDim.x + threadIdx.x) >> 5;
    int lane = threadIdx.x & 31;
    if (node >= N) return;
    int off = g_offs[node];
    int deg = g_offs[node + 1] - off;
    float dnode = g_d[node];
    float eself = leaky(g_s[node] + dnode);

    // pass 1: segment max (incl. self loop)
    float m = eself;
    for (int j = lane; j < deg; j += 32)
        m = fmaxf(m, leaky(g_s[g_csr[off + j]] + dnode));
#pragma unroll
    for (int o = 16; o; o >>= 1)
        m = fmaxf(m, __shfl_xor_sync(0xffffffffu, m, o));

    // pass 2: weighted accumulation
    float exs = exp2f((eself - m) * LOG2E);
    float a0 = exs * g_h[node * 64 + lane];
    float a1 = exs * g_h[node * 64 + lane + 32];
    float dsum = 0.f;
    for (int r = 0; r < deg; r += 32) {
        int j = r + lane;
        int sv = 0;
        float exv = 0.f;
        if (j < deg) {
            sv = g_csr[off + j];
            exv = exp2f((leaky(g_s[sv] + dnode) - m) * LOG2E);
        }
        dsum += exv;
        int cnt = min(32, deg - r);
        if (cnt == 32) {
#pragma unroll 8
            for (int k = 0; k < 32; k++) {
                int sj = __shfl_sync(0xffffffffu, sv, k);
                float exj = __shfl_sync(0xffffffffu, exv, k);
                a0 += exj * g_h[sj * 64 + lane];
                a1 += exj * g_h[sj * 64 + lane + 32];
            }
        } else {
            for (int k = 0; k < cnt; k++) {
                int sj = __shfl_sync(0xffffffffu, sv, k);
                float exj = __shfl_sync(0xffffffffu, exv, k);
                a0 += exj * g_h[sj * 64 + lane];
                a1 += exj * g_h[sj * 64 + lane + 32];
            }
        }
    }
#pragma unroll
    for (int o = 16; o; o >>= 1) dsum += __shfl_xor_sync(0xffffffffu, dsum, o);
    float inv = 1.f / (exs + dsum);
    float o0 = a0 * inv + b[lane];
    float o1 = a1 * inv + b[lane + 32];
    if (RELU) { o0 = fmaxf(o0, 0.f); o1 = fmaxf(o1, 0.f); }
    g_x[node * 64 + lane] = o0;
    g_x[node * 64 + lane + 32] = o1;
}

// H=1 (layer 3), warp per dst node, writes final output.
__global__ void gat1(const float* __restrict__ b3, float* __restrict__ out, int N) {
    int node = (blockIdx.x * blockDim.x + threadIdx.x) >> 5;
    int lane = threadIdx.x & 31;
    if (node >= N) return;
    int off = g_offs[node];
    int deg = g_offs[node + 1] - off;
    float dnode = g_d[node];
    float eself = leaky(g_s[node] + dnode);

    float m = eself;
    for (int j = lane; j < deg; j += 32)
        m = fmaxf(m, leaky(g_s[g_csr[off + j]] + dnode));
#pragma unroll
    for (int o = 16; o; o >>= 1)
        m = fmaxf(m, __shfl_xor_sync(0xffffffffu, m, o));

    float dsum = 0.f, acc = 0.f;
    for (int j = lane; j < deg; j += 32) {
        int sv = g_csr[off + j];
        float exv = exp2f((leaky(g_s[sv] + dnode) - m) * LOG2E);
        dsum += exv;
        acc += exv * g_h[sv];
    }
#pragma unroll
    for (int o = 16; o; o >>= 1) {
        dsum += __shfl_xor_sync(0xffffffffu, dsum, o);
        acc += __shfl_xor_sync(0xffffffffu, acc, o);
    }
    if (lane == 0) {
        float exs = exp2f((eself - m) * LOG2E);
        dsum += exs;
        acc += exs * g_h[node];
        out[node] = acc / dsum + b3[0];
    }
}

extern "C" void kernel_launch(void* const* d_in, const int* in_sizes, int n_in,
                              void* d_out, int out_size) {
    const float* x   = (const float*)d_in[0];
    const int*   ei  = (const int*)d_in[1];
    const float* W1  = (const float*)d_in[3];
    const float* as1 = (const float*)d_in[4];
    const float* ad1 = (const float*)d_in[5];
    const float* b1  = (const float*)d_in[6];
    const float* W2  = (const float*)d_in[7];
    const float* as2 = (const float*)d_in[8];
    const float* ad2 = (const float*)d_in[9];
    const float* b2  = (const float*)d_in[10];
    const float* W3  = (const float*)d_in[11];
    const float* as3 = (const float*)d_in[12];
    const float* ad3 = (const float*)d_in[13];
    const float* b3  = (const float*)d_in[14];

    int N = in_sizes[0];       // x is [N,1]
    int E = in_sizes[1] / 2;   // edge_index is [2,E]
    const int* src = ei;
    const int* dst = ei + E;

    const int TB = 256;
    int gN    = (N + TB - 1) / TB;
    int gN16  = (N * 16 + TB - 1) / TB;
    int gN32  = (N * 32 + TB - 1) / TB;   // warp-per-node kernels
    int gE    = (E + TB - 1) / TB;
    int nb    = (N + 255) / 256;          // scan blocks (<=256 required)

    // ---- CSR build (once per launch; edges reused by all 3 layers) ----
    deg_zero<<<gN, TB>>>(N);
    deg_hist<<<gE, TB>>>(dst, E);
    scanA<<<nb, 256>>>(N);
    scanB<<<1, 256>>>(nb);
    scanC<<<gN, TB>>>(N);
    scatter<<<gE, TB>>>(src, dst, E);

    // ---- Layer 1 ----
    transform1<<<gN16, TB>>>(x, W1, as1, ad1, N);
    gat64<true><<<gN32, TB>>>(b1, N);

    // ---- Layer 2 ----
    transform2<<<gN32, TB>>>(W2, as2, ad2, N);
    gat64<true><<<gN32, TB>>>(b2, N);

    // ---- Layer 3 ----
    transform3<<<gN32, TB>>>(W3, as3, ad3, N);
    gat1<<<gN32, TB>>>(b3, (float*)d_out, N);
}

// round 3
// speedup vs baseline: 2.2538x; 1.3540x over previous
#include <cuda_runtime.h>

#define MAXN 50176
#define MAXE 1700000
#define LOG2E 1.4426950408889634f

// Scratch (__device__ globals; no allocation allowed)
__device__ __align__(256) float g_h2[MAXN * 64];  // layer-2 transformed features
__device__ float g_s1[MAXN], g_d1[MAXN];
__device__ float g_s2[MAXN], g_d2[MAXN];
__device__ float g_h3[MAXN], g_s3[MAXN], g_d3[MAXN];
__device__ int g_deg[MAXN];
__device__ int g_offs[MAXN + 1];
__device__ int g_loc[MAXN];
__device__ int g_cursor[MAXN];
__device__ int g_csr[MAXE];
__device__ int g_bsums[256];

__device__ __forceinline__ float leaky(float v) { return v > 0.f ? v : 0.2f * v; }

// ======================= prep: layer-1 s/d scalars + deg zero =======================
// s1_i = x_i * (W1 . as1),  d1_i = x_i * (W1 . ad1)   (rank-1 layer 1)
__global__ void prep1(const float* __restrict__ x, const float* __restrict__ W1,
                      const float* __restrict__ as1, const float* __restrict__ ad1, int N) {
    __shared__ float cs_sh, cd_sh;
    if (threadIdx.x == 0) {
        float cs = 0.f, cd = 0.f;
#pragma unroll
        for (int j = 0; j < 64; j++) { cs += W1[j] * as1[j]; cd += W1[j] * ad1[j]; }
        cs_sh = cs; cd_sh = cd;
    }
    __syncthreads();
    int i = blockIdx.x * blockDim.x + threadIdx.x;
    if (i >= N) return;
    float xv = x[i];
    g_s1[i] = xv * cs_sh;
    g_d1[i] = xv * cd_sh;
    g_deg[i] = 0;
}

// ======================= CSR build =======================
__global__ void deg_hist(const int* __restrict__ dst, int E) {
    int e = blockIdx.x * blockDim.x + threadIdx.x;
    if (e < E) atomicAdd(&g_deg[dst[e]], 1);
}

__global__ void scanA(int N) {
    __shared__ int sm[256];
    int t = threadIdx.x;
    int i = blockIdx.x * 256 + t;
    int v = (i < N) ? g_deg[i] : 0;
    sm[t] = v;
    __syncthreads();
#pragma unroll
    for (int o = 1; o < 256; o <<= 1) {
        int x = (t >= o) ? sm[t - o] : 0;
        __syncthreads();
        sm[t] += x;
        __syncthreads();
    }
    if (i < N) g_loc[i] = sm[t] - v;
    if (t == 255) g_bsums[blockIdx.x] = sm[255];
}

__global__ void scanB(int nb) {
    __shared__ int sm[256];
    int t = threadIdx.x;
    int v = (t < nb) ? g_bsums[t] : 0;
    sm[t] = v;
    __syncthreads();
#pragma unroll
    for (int o = 1; o < 256; o <<= 1) {
        int x = (t >= o) ? sm[t - o] : 0;
        __syncthreads();
        sm[t] += x;
        __syncthreads();
    }
    if (t < nb) g_bsums[t] = sm[t] - v;
}

__global__ void scanC(int N) {
    int i = blockIdx.x * blockDim.x + threadIdx.x;
    if (i >= N) return;
    int off = g_loc[i] + g_bsums[i >> 8];
    g_offs[i] = off;
    g_cursor[i] = off;
    if (i == N - 1) g_offs[N] = off + g_deg[i];
}

__global__ void scatter(const int* __restrict__ src, const int* __restrict__ dst, int E) {
    int e = blockIdx.x * blockDim.x + threadIdx.x;
    if (e >= E) return;
    int d = dst[e];
    int pos = atomicAdd(&g_cursor[d], 1);
    g_csr[pos] = src[e];
}

// ======================= Fused layer-1 GAT (scalar) + layer-2 transform =======================
// Warp per node: z = GAT_scalar(x) ; v = relu(z*W1+b1) ; h2 = v@W2 ; s2,d2 = h2.a
__global__ void gat_l1_fused(const float* __restrict__ x,
                             const float* __restrict__ W1, const float* __restrict__ b1,
                             const float* __restrict__ W2,
                             const float* __restrict__ as2, const float* __restrict__ ad2, int N) {
    int node = (blockIdx.x * blockDim.x + threadIdx.x) >> 5;
    int lane = threadIdx.x & 31;
    if (node >= N) return;
    int off = g_offs[node];
    int deg = g_offs[node + 1] - off;
    float dn = g_d1[node];
    float es = leaky(g_s1[node] + dn);

    // segment max (incl. self loop)
    float m = es;
    for (int j = lane; j < deg; j += 32)
        m = fmaxf(m, leaky(g_s1[g_csr[off + j]] + dn));
#pragma unroll
    for (int o = 16; o; o >>= 1)
        m = fmaxf(m, __shfl_xor_sync(0xffffffffu, m, o));

    // scalar weighted aggregation of x
    float dsum = 0.f, zacc = 0.f;
    for (int j = lane; j < deg; j += 32) {
        int sv = g_csr[off + j];
        float exv = exp2f((leaky(g_s1[sv] + dn) - m) * LOG2E);
        dsum += exv;
        zacc += exv * x[sv];
    }
#pragma unroll
    for (int o = 16; o; o >>= 1) {
        dsum += __shfl_xor_sync(0xffffffffu, dsum, o);
        zacc += __shfl_xor_sync(0xffffffffu, zacc, o);
    }
    float exs = exp2f((es - m) * LOG2E);
    float z = (zacc + exs * x[node]) / (dsum + exs);

    // out1 row as function of z, then layer-2 transform (64x64 matvec via shfl)
    float v0 = fmaxf(z * W1[lane] + b1[lane], 0.f);
    float v1 = fmaxf(z * W1[lane + 32] + b1[lane + 32], 0.f);
    float o0 = 0.f, o1 = 0.f;
#pragma unroll
    for (int k = 0; k < 64; k++) {
        float vk = __shfl_sync(0xffffffffu, (k < 32) ? v0 : v1, k & 31);
        o0 += vk * W2[k * 64 + lane];
        o1 += vk * W2[k * 64 + lane + 32];
    }
    g_h2[node * 64 + lane] = o0;
    g_h2[node * 64 + lane + 32] = o1;
    float ps = o0 * as2[lane] + o1 * as2[lane + 32];
    float pd = o0 * ad2[lane] + o1 * ad2[lane + 32];
#pragma unroll
    for (int o = 16; o; o >>= 1) {
        ps += __shfl_down_sync(0xffffffffu, ps, o);
        pd += __shfl_down_sync(0xffffffffu, pd, o);
    }
    if (lane == 0) { g_s2[node] = ps; g_d2[node] = pd; }
}

// ======================= Layer-2 wide GAT + fused layer-3 transform =======================
// Warp per node: out2 = GAT64(h2); h3 = relu(out2).W3 ; s3,d3
__global__ void gat_l2(const float* __restrict__ b2, const float* __restrict__ W3,
                       const float* __restrict__ as3, const float* __restrict__ ad3, int N) {
    int node = (blockIdx.x * blockDim.x + threadIdx.x) >> 5;
    int lane = threadIdx.x & 31;
    if (node >= N) return;
    int off = g_offs[node];
    int deg = g_offs[node + 1] - off;
    float dn = g_d2[node];
    float es = leaky(g_s2[node] + dn);

    // segment max
    float m = es;
    for (int j = lane; j < deg; j += 32)
        m = fmaxf(m, leaky(g_s2[g_csr[off + j]] + dn));
#pragma unroll
    for (int o = 16; o; o >>= 1)
        m = fmaxf(m, __shfl_xor_sync(0xffffffffu, m, o));

    // weighted 64-wide gather
    float exs = exp2f((es - m) * LOG2E);
    float a0 = exs * g_h2[node * 64 + lane];
    float a1 = exs * g_h2[node * 64 + lane + 32];
    float dsum = 0.f;
    for (int r = 0; r < deg; r += 32) {
        int j = r + lane;
        int sv = 0;
        float exv = 0.f;
        if (j < deg) {
            sv = g_csr[off + j];
            exv = exp2f((leaky(g_s2[sv] + dn) - m) * LOG2E);
        }
        dsum += exv;
        int cnt = min(32, deg - r);
        if (cnt == 32) {
#pragma unroll 8
            for (int k = 0; k < 32; k++) {
                int sj = __shfl_sync(0xffffffffu, sv, k);
                float exj = __shfl_sync(0xffffffffu, exv, k);
                a0 += exj * g_h2[sj * 64 + lane];
                a1 += exj * g_h2[sj * 64 + lane + 32];
            }
        } else {
            for (int k = 0; k < cnt; k++) {
                int sj = __shfl_sync(0xffffffffu, sv, k);
                float exj = __shfl_sync(0xffffffffu, exv, k);
                a0 += exj * g_h2[sj * 64 + lane];
                a1 += exj * g_h2[sj * 64 + lane + 32];
            }
        }
    }
#pragma unroll
    for (int o = 16; o; o >>= 1) dsum += __shfl_xor_sync(0xffffffffu, dsum, o);
    float inv = 1.f / (exs + dsum);
    // x3 = relu(out2 + b2), then fused layer-3 transform: h3 = x3 . W3
    float x30 = fmaxf(a0 * inv + b2[lane], 0.f);
    float x31 = fmaxf(a1 * inv + b2[lane + 32], 0.f);
    float p = x30 * W3[lane] + x31 * W3[lane + 32];
#pragma unroll
    for (int o = 16; o; o >>= 1) p += __shfl_down_sync(0xffffffffu, p, o);
    if (lane == 0) {
        g_h3[node] = p;
        g_s3[node] = p * as3[0];
        g_d3[node] = p * ad3[0];
    }
}

// ======================= Layer-3 scalar GAT -> output =======================
__global__ void gat_out(const float* __restrict__ b3, float* __restrict__ out, int N) {
    int node = (blockIdx.x * blockDim.x + threadIdx.x) >> 5;
    int lane = threadIdx.x & 31;
    if (node >= N) return;
    int off = g_offs[node];
    int deg = g_offs[node + 1] - off;
    float dn = g_d3[node];
    float es = leaky(g_s3[node] + dn);

    float m = es;
    for (int j = lane; j < deg; j += 32)
        m = fmaxf(m, leaky(g_s3[g_csr[off + j]] + dn));
#pragma unroll
    for (int o = 16; o; o >>= 1)
        m = fmaxf(m, __shfl_xor_sync(0xffffffffu, m, o));

    float dsum = 0.f, acc = 0.f;
    for (int j = lane; j < deg; j += 32) {
        int sv = g_csr[off + j];
        float exv = exp2f((leaky(g_s3[sv] + dn) - m) * LOG2E);
        dsum += exv;
        acc += exv * g_h3[sv];
    }
#pragma unroll
    for (int o = 16; o; o >>= 1) {
        dsum += __shfl_xor_sync(0xffffffffu, dsum, o);
        acc += __shfl_xor_sync(0xffffffffu, acc, o);
    }
    if (lane == 0) {
        float exs = exp2f((es - m) * LOG2E);
        out[node] = (acc + exs * g_h3[node]) / (dsum + exs) + b3[0];
    }
}

extern "C" void kernel_launch(void* const* d_in, const int* in_sizes, int n_in,
                              void* d_out, int out_size) {
    const float* x   = (const float*)d_in[0];
    const int*   ei  = (const int*)d_in[1];
    const float* W1  = (const float*)d_in[3];
    const float* as1 = (const float*)d_in[4];
    const float* ad1 = (const float*)d_in[5];
    const float* b1  = (const float*)d_in[6];
    const float* W2  = (const float*)d_in[7];
    const float* as2 = (const float*)d_in[8];
    const float* ad2 = (const float*)d_in[9];
    const float* b2  = (const float*)d_in[10];
    const float* W3  = (const float*)d_in[11];
    const float* as3 = (const float*)d_in[12];
    const float* ad3 = (const float*)d_in[13];
    const float* b3  = (const float*)d_in[14];

    int N = in_sizes[0];
    int E = in_sizes[1] / 2;
    const int* src = ei;
    const int* dst = ei + E;

    const int TB = 256;
    int gN   = (N + TB - 1) / TB;
    int gN32 = (N * 32 + TB - 1) / TB;
    int gE   = (E + TB - 1) / TB;
    int nb   = (N + 255) / 256;

    // prep + CSR build
    prep1<<<gN, TB>>>(x, W1, as1, ad1, N);
    deg_hist<<<gE, TB>>>(dst, E);
    scanA<<<nb, 256>>>(N);
    scanB<<<1, 256>>>(nb);
    scanC<<<gN, TB>>>(N);
    scatter<<<gE, TB>>>(src, dst, E);

    // layer 1 (scalar GAT) fused with layer-2 transform
    gat_l1_fused<<<gN32, TB>>>(x, W1, b1, W2, as2, ad2, N);
    // layer 2 (wide GAT) fused with layer-3 transform
    gat_l2<<<gN32, TB>>>(b2, W3, as3, ad3, N);
    // layer 3 (scalar GAT) -> output
    gat_out<<<gN32, TB>>>(b3, (float*)d_out, N);
}

// round 4
// speedup vs baseline: 2.4936x; 1.1064x over previous
#include <cuda_runtime.h>

#define MAXN 50176
#define MAXE 1700000
#define LOG2E 1.4426950408889634f

// Scratch (__device__ globals; no allocation allowed)
__device__ __align__(256) float g_h2[MAXN * 64];   // layer-2 transformed features
__device__ __align__(16) float2 g_sx1[MAXN];       // packed (s1, x) for layer-1 gathers
__device__ __align__(16) float2 g_sh3[MAXN];       // packed (s3, h3) for layer-3 gathers
__device__ float g_d1[MAXN];
__device__ float g_s2[MAXN], g_d2[MAXN];
__device__ float g_d3[MAXN];
__device__ int g_deg[MAXN];
__device__ int g_offs[MAXN + 1];
__device__ int g_loc[MAXN];
__device__ int g_cursor[MAXN];
__device__ int g_csr[MAXE];
__device__ int g_bsums[256];

__device__ __forceinline__ float leaky(float v) { return v > 0.f ? v : 0.2f * v; }

// ======================= prep: layer-1 scalars (rank-1) + deg zero =======================
__global__ void prep1(const float* __restrict__ x, const float* __restrict__ W1,
                      const float* __restrict__ as1, const float* __restrict__ ad1, int N) {
    __shared__ float cs_sh, cd_sh;
    if (threadIdx.x == 0) {
        float cs = 0.f, cd = 0.f;
#pragma unroll
        for (int j = 0; j < 64; j++) { cs += W1[j] * as1[j]; cd += W1[j] * ad1[j]; }
        cs_sh = cs; cd_sh = cd;
    }
    __syncthreads();
    int i = blockIdx.x * blockDim.x + threadIdx.x;
    if (i >= N) return;
    float xv = x[i];
    g_sx1[i] = make_float2(xv * cs_sh, xv);
    g_d1[i] = xv * cd_sh;
    g_deg[i] = 0;
}

// ======================= CSR build =======================
__global__ void deg_hist(const int* __restrict__ dst, int E) {
    int e = blockIdx.x * blockDim.x + threadIdx.x;
    if (e < E) atomicAdd(&g_deg[dst[e]], 1);
}

// Block-local exclusive scan (256/block); writes block totals.
__global__ void scanA(int N) {
    __shared__ int sm[256];
    int t = threadIdx.x;
    int i = blockIdx.x * 256 + t;
    int v = (i < N) ? g_deg[i] : 0;
    sm[t] = v;
    __syncthreads();
#pragma unroll
    for (int o = 1; o < 256; o <<= 1) {
        int x = (t >= o) ? sm[t - o] : 0;
        __syncthreads();
        sm[t] += x;
        __syncthreads();
    }
    if (i < N) g_loc[i] = sm[t] - v;
    if (t == 255) g_bsums[blockIdx.x] = sm[255];
}

// Folded scanB+scanC: block b's offset = sum(bsums[0..b-1]) via warp reduce.
__global__ void scanC(int N) {
    __shared__ int boff_sh;
    int b = blockIdx.x;
    if (threadIdx.x < 32) {
        int acc = 0;
        for (int j = threadIdx.x; j < b; j += 32) acc += g_bsums[j];
#pragma unroll
        for (int o = 16; o; o >>= 1) acc += __shfl_xor_sync(0xffffffffu, acc, o);
        if (threadIdx.x == 0) boff_sh = acc;
    }
    __syncthreads();
    int i = b * 256 + threadIdx.x;
    if (i >= N) return;
    int off = g_loc[i] + boff_sh;
    g_offs[i] = off;
    g_cursor[i] = off;
    if (i == N - 1) g_offs[N] = off + g_deg[i];
}

__global__ void scatter(const int* __restrict__ src, const int* __restrict__ dst, int E) {
    int e = blockIdx.x * blockDim.x + threadIdx.x;
    if (e >= E) return;
    int d = dst[e];
    int pos = atomicAdd(&g_cursor[d], 1);
    g_csr[pos] = src[e];
}

// ======================= Layer 1 (scalar GAT, no max shift) + layer-2 transform =======================
__global__ void gat_l1_fused(const float* __restrict__ W1, const float* __restrict__ b1,
                             const float* __restrict__ W2,
                             const float* __restrict__ as2, const float* __restrict__ ad2, int N) {
    int node = (blockIdx.x * blockDim.x + threadIdx.x) >> 5;
    int lane = threadIdx.x & 31;
    if (node >= N) return;
    int off = g_offs[node];
    int deg = g_offs[node + 1] - off;
    float dn = g_d1[node];
    float2 self = g_sx1[node];

    float dsum = 0.f, zacc = 0.f;
    for (int j = lane; j < deg; j += 32) {
        int sv = g_csr[off + j];
        float2 t = g_sx1[sv];
        float ex = exp2f(leaky(t.x + dn) * LOG2E);
        dsum += ex;
        zacc += ex * t.y;
    }
#pragma unroll
    for (int o = 16; o; o >>= 1) {
        dsum += __shfl_xor_sync(0xffffffffu, dsum, o);
        zacc += __shfl_xor_sync(0xffffffffu, zacc, o);
    }
    float exs = exp2f(leaky(self.x + dn) * LOG2E);
    float z = (zacc + exs * self.y) / (dsum + exs);

    // out1 row = relu(z*W1+b1); layer-2 transform h2 = out1 @ W2 (64x64 via shfl)
    float v0 = fmaxf(z * W1[lane] + b1[lane], 0.f);
    float v1 = fmaxf(z * W1[lane + 32] + b1[lane + 32], 0.f);
    float o0 = 0.f, o1 = 0.f;
#pragma unroll
    for (int k = 0; k < 64; k++) {
        float vk = __shfl_sync(0xffffffffu, (k < 32) ? v0 : v1, k & 31);
        o0 += vk * W2[k * 64 + lane];
        o1 += vk * W2[k * 64 + lane + 32];
    }
    g_h2[node * 64 + lane] = o0;
    g_h2[node * 64 + lane + 32] = o1;
    float ps = o0 * as2[lane] + o1 * as2[lane + 32];
    float pd = o0 * ad2[lane] + o1 * ad2[lane + 32];
#pragma unroll
    for (int o = 16; o; o >>= 1) {
        ps += __shfl_down_sync(0xffffffffu, ps, o);
        pd += __shfl_down_sync(0xffffffffu, pd, o);
    }
    if (lane == 0) { g_s2[node] = ps; g_d2[node] = pd; }
}

// ======================= Layer 2 (wide GAT, no max shift) + layer-3 transform =======================
__global__ void gat_l2(const float* __restrict__ b2, const float* __restrict__ W3,
                       const float* __restrict__ as3, const float* __restrict__ ad3, int N) {
    int node = (blockIdx.x * blockDim.x + threadIdx.x) >> 5;
    int lane = threadIdx.x & 31;
    if (node >= N) return;
    int off = g_offs[node];
    int deg = g_offs[node + 1] - off;
    float dn = g_d2[node];

    float exs = exp2f(leaky(g_s2[node] + dn) * LOG2E);
    float a0 = exs * g_h2[node * 64 + lane];
    float a1 = exs * g_h2[node * 64 + lane + 32];
    float dsum = 0.f;
    for (int r = 0; r < deg; r += 32) {
        int j = r + lane;
        int sv = 0;
        float exv = 0.f;
        if (j < deg) {
            sv = g_csr[off + j];
            exv = exp2f(leaky(g_s2[sv] + dn) * LOG2E);
        }
        dsum += exv;
        int cnt = min(32, deg - r);
        if (cnt == 32) {
#pragma unroll 8
            for (int k = 0; k < 32; k++) {
                int sj = __shfl_sync(0xffffffffu, sv, k);
                float exj = __shfl_sync(0xffffffffu, exv, k);
                a0 += exj * g_h2[sj * 64 + lane];
                a1 += exj * g_h2[sj * 64 + lane + 32];
            }
        } else {
            for (int k = 0; k < cnt; k++) {
                int sj = __shfl_sync(0xffffffffu, sv, k);
                float exj = __shfl_sync(0xffffffffu, exv, k);
                a0 += exj * g_h2[sj * 64 + lane];
                a1 += exj * g_h2[sj * 64 + lane + 32];
            }
        }
    }
#pragma unroll
    for (int o = 16; o; o >>= 1) dsum += __shfl_xor_sync(0xffffffffu, dsum, o);
    float inv = 1.f / (exs + dsum);
    // x3 = relu(out2 + b2); fused layer-3 projection h3 = x3 . W3
    float x30 = fmaxf(a0 * inv + b2[lane], 0.f);
    float x31 = fmaxf(a1 * inv + b2[lane + 32], 0.f);
    float p = x30 * W3[lane] + x31 * W3[lane + 32];
#pragma unroll
    for (int o = 16; o; o >>= 1) p += __shfl_down_sync(0xffffffffu, p, o);
    if (lane == 0) {
        g_sh3[node] = make_float2(p * as3[0], p);
        g_d3[node] = p * ad3[0];
    }
}

// ======================= Layer 3 (scalar GAT, no max shift) -> output =======================
__global__ void gat_out(const float* __restrict__ b3, float* __restrict__ out, int N) {
    int node = (blockIdx.x * blockDim.x + threadIdx.x) >> 5;
    int lane = threadIdx.x & 31;
    if (node >= N) return;
    int off = g_offs[node];
    int deg = g_offs[node + 1] - off;
    float dn = g_d3[node];
    float2 self = g_sh3[node];

    float dsum = 0.f, acc = 0.f;
    for (int j = lane; j < deg; j += 32) {
        int sv = g_csr[off + j];
        float2 t = g_sh3[sv];
        float ex = exp2f(leaky(t.x + dn) * LOG2E);
        dsum += ex;
        acc += ex * t.y;
    }
#pragma unroll
    for (int o = 16; o; o >>= 1) {
        dsum += __shfl_xor_sync(0xffffffffu, dsum, o);
        acc += __shfl_xor_sync(0xffffffffu, acc, o);
    }
    if (lane == 0) {
        float exs = exp2f(leaky(self.x + dn) * LOG2E);
        out[node] = (acc + exs * self.y) / (dsum + exs) + b3[0];
    }
}

extern "C" void kernel_launch(void* const* d_in, const int* in_sizes, int n_in,
                              void* d_out, int out_size) {
    const float* x   = (const float*)d_in[0];
    const int*   ei  = (const int*)d_in[1];
    const float* W1  = (const float*)d_in[3];
    const float* as1 = (const float*)d_in[4];
    const float* ad1 = (const float*)d_in[5];
    const float* b1  = (const float*)d_in[6];
    const float* W2  = (const float*)d_in[7];
    const float* as2 = (const float*)d_in[8];
    const float* ad2 = (const float*)d_in[9];
    const float* b2  = (const float*)d_in[10];
    const float* W3  = (const float*)d_in[11];
    const float* as3 = (const float*)d_in[12];
    const float* ad3 = (const float*)d_in[13];
    const float* b3  = (const float*)d_in[14];

    int N = in_sizes[0];
    int E = in_sizes[1] / 2;
    const int* src = ei;
    const int* dst = ei + E;

    const int TB = 256;
    int gN   = (N + TB - 1) / TB;
    int gN32 = (N * 32 + TB - 1) / TB;
    int gE   = (E + TB - 1) / TB;
    int nb   = (N + 255) / 256;

    // prep + CSR build
    prep1<<<gN, TB>>>(x, W1, as1, ad1, N);
    deg_hist<<<gE, TB>>>(dst, E);
    scanA<<<nb, 256>>>(N);
    scanC<<<nb, 256>>>(N);
    scatter<<<gE, TB>>>(src, dst, E);

    // fused layers
    gat_l1_fused<<<gN32, TB>>>(W1, b1, W2, as2, ad2, N);
    gat_l2<<<gN32, TB>>>(b2, W3, as3, ad3, N);
    gat_out<<<gN32, TB>>>(b3, (float*)d_out, N);
}

// round 5
// speedup vs baseline: 2.7024x; 1.0837x over previous
#include <cuda_runtime.h>
#include <cuda_fp16.h>

#define MAXN 50176
#define MAXE 1700000
#define LOG2E 1.4426950408889634f

// Scratch (__device__ globals; no allocation allowed)
__device__ __align__(256) __half2 g_h2h[MAXN * 32];  // layer-2 features, fp16 packed (feat 2k,2k+1 in slot k)
__device__ __align__(16) float2 g_sx1[MAXN];         // packed (s1, x)
__device__ __align__(16) float2 g_sh3[MAXN];         // packed (s3, h3)
__device__ float g_d1[MAXN];
__device__ float g_s2[MAXN], g_d2[MAXN];
__device__ float g_d3[MAXN];
__device__ int g_deg[MAXN];
__device__ int g_offs[MAXN + 1];
__device__ int g_loc[MAXN];
__device__ int g_cursor[MAXN];
__device__ int g_csr[MAXE];
__device__ int g_bsums[256];

__device__ __forceinline__ float leaky(float v) { return v > 0.f ? v : 0.2f * v; }

// ======================= prep: layer-1 scalars (rank-1) + deg zero =======================
__global__ void prep1(const float* __restrict__ x, const float* __restrict__ W1,
                      const float* __restrict__ as1, const float* __restrict__ ad1, int N) {
    __shared__ float cs_sh, cd_sh;
    if (threadIdx.x == 0) {
        float cs = 0.f, cd = 0.f;
#pragma unroll
        for (int j = 0; j < 64; j++) { cs += W1[j] * as1[j]; cd += W1[j] * ad1[j]; }
        cs_sh = cs; cd_sh = cd;
    }
    __syncthreads();
    int i = blockIdx.x * blockDim.x + threadIdx.x;
    if (i >= N) return;
    float xv = x[i];
    g_sx1[i] = make_float2(xv * cs_sh, xv);
    g_d1[i] = xv * cd_sh;
    g_deg[i] = 0;
}

// ======================= CSR build =======================
__global__ void deg_hist(const int* __restrict__ dst, int E) {
    int e = blockIdx.x * blockDim.x + threadIdx.x;
    if (e < E) atomicAdd(&g_deg[dst[e]], 1);
}

__global__ void scanA(int N) {
    __shared__ int sm[256];
    int t = threadIdx.x;
    int i = blockIdx.x * 256 + t;
    int v = (i < N) ? g_deg[i] : 0;
    sm[t] = v;
    __syncthreads();
#pragma unroll
    for (int o = 1; o < 256; o <<= 1) {
        int x = (t >= o) ? sm[t - o] : 0;
        __syncthreads();
        sm[t] += x;
        __syncthreads();
    }
    if (i < N) g_loc[i] = sm[t] - v;
    if (t == 255) g_bsums[blockIdx.x] = sm[255];
}

// Folded scanB+scanC: block b's offset = sum(bsums[0..b-1]) via warp reduce.
__global__ void scanC(int N) {
    __shared__ int boff_sh;
    int b = blockIdx.x;
    if (threadIdx.x < 32) {
        int acc = 0;
        for (int j = threadIdx.x; j < b; j += 32) acc += g_bsums[j];
#pragma unroll
        for (int o = 16; o; o >>= 1) acc += __shfl_xor_sync(0xffffffffu, acc, o);
        if (threadIdx.x == 0) boff_sh = acc;
    }
    __syncthreads();
    int i = b * 256 + threadIdx.x;
    if (i >= N) return;
    int off = g_loc[i] + boff_sh;
    g_offs[i] = off;
    g_cursor[i] = off;
    if (i == N - 1) g_offs[N] = off + g_deg[i];
}

__global__ void scatter(const int* __restrict__ src, const int* __restrict__ dst, int E) {
    int e = blockIdx.x * blockDim.x + threadIdx.x;
    if (e >= E) return;
    int d = dst[e];
    int pos = atomicAdd(&g_cursor[d], 1);
    g_csr[pos] = src[e];
}

// ======================= Layer 1 (scalar GAT) + layer-2 transform (fp16 pack) =======================
// Lane k computes features (2k, 2k+1) so the half2 pack is free.
__global__ void gat_l1_fused(const float* __restrict__ W1, const float* __restrict__ b1,
                             const float* __restrict__ W2,
                             const float* __restrict__ as2, const float* __restrict__ ad2, int N) {
    int node = (blockIdx.x * blockDim.x + threadIdx.x) >> 5;
    int lane = threadIdx.x & 31;
    if (node >= N) return;
    int off = g_offs[node];
    int deg = g_offs[node + 1] - off;
    float dn = g_d1[node];
    float2 self = g_sx1[node];

    float dsum = 0.f, zacc = 0.f;
    for (int j = lane; j < deg; j += 32) {
        int sv = g_csr[off + j];
        float2 t = g_sx1[sv];
        float ex = exp2f(leaky(t.x + dn) * LOG2E);
        dsum += ex;
        zacc += ex * t.y;
    }
#pragma unroll
    for (int o = 16; o; o >>= 1) {
        dsum += __shfl_xor_sync(0xffffffffu, dsum, o);
        zacc += __shfl_xor_sync(0xffffffffu, zacc, o);
    }
    float exs = exp2f(leaky(self.x + dn) * LOG2E);
    float z = (zacc + exs * self.y) / (dsum + exs);

    // out1 = relu(z*W1+b1): lane holds features lane and lane+32 (for shfl broadcast)
    float v0 = fmaxf(z * W1[lane] + b1[lane], 0.f);
    float v1 = fmaxf(z * W1[lane + 32] + b1[lane + 32], 0.f);
    // h2 features 2*lane, 2*lane+1
    float o0 = 0.f, o1 = 0.f;
#pragma unroll
    for (int k = 0; k < 64; k++) {
        float vk = __shfl_sync(0xffffffffu, (k < 32) ? v0 : v1, k & 31);
        float2 w = ((const float2*)W2)[k * 32 + lane];
        o0 += vk * w.x;
        o1 += vk * w.y;
    }
    g_h2h[node * 32 + lane] = __floats2half2_rn(o0, o1);
    float2 a_s = ((const float2*)as2)[lane];
    float2 a_d = ((const float2*)ad2)[lane];
    float ps = o0 * a_s.x + o1 * a_s.y;
    float pd = o0 * a_d.x + o1 * a_d.y;
#pragma unroll
    for (int o = 16; o; o >>= 1) {
        ps += __shfl_down_sync(0xffffffffu, ps, o);
        pd += __shfl_down_sync(0xffffffffu, pd, o);
    }
    if (lane == 0) { g_s2[node] = ps; g_d2[node] = pd; }
}

// ======================= Layer 2 (wide GAT, fp16 gather) + layer-3 transform =======================
__global__ void gat_l2(const float* __restrict__ b2, const float* __restrict__ W3,
                       const float* __restrict__ as3, const float* __restrict__ ad3, int N) {
    int node = (blockIdx.x * blockDim.x + threadIdx.x) >> 5;
    int lane = threadIdx.x & 31;
    if (node >= N) return;
    int off = g_offs[node];
    int deg = g_offs[node + 1] - off;
    float dn = g_d2[node];

    float exs = exp2f(leaky(g_s2[node] + dn) * LOG2E);
    float2 hself = __half22float2(g_h2h[node * 32 + lane]);
    float a0 = exs * hself.x;
    float a1 = exs * hself.y;
    float dsum = 0.f;
    for (int r = 0; r < deg; r += 32) {
        int j = r + lane;
        int sv = 0;
        float exv = 0.f;
        if (j < deg) {
            sv = g_csr[off + j];
            exv = exp2f(leaky(g_s2[sv] + dn) * LOG2E);
        }
        dsum += exv;
        int cnt = min(32, deg - r);
        if (cnt == 32) {
#pragma unroll 8
            for (int k = 0; k < 32; k++) {
                int sj = __shfl_sync(0xffffffffu, sv, k);
                float exj = __shfl_sync(0xffffffffu, exv, k);
                float2 hv = __half22float2(g_h2h[sj * 32 + lane]);
                a0 += exj * hv.x;
                a1 += exj * hv.y;
            }
        } else {
            for (int k = 0; k < cnt; k++) {
                int sj = __shfl_sync(0xffffffffu, sv, k);
                float exj = __shfl_sync(0xffffffffu, exv, k);
                float2 hv = __half22float2(g_h2h[sj * 32 + lane]);
                a0 += exj * hv.x;
                a1 += exj * hv.y;
            }
        }
    }
#pragma unroll
    for (int o = 16; o; o >>= 1) dsum += __shfl_xor_sync(0xffffffffu, dsum, o);
    float inv = 1.f / (exs + dsum);
    float2 bb = ((const float2*)b2)[lane];
    float2 w3 = ((const float2*)W3)[lane];
    float x30 = fmaxf(a0 * inv + bb.x, 0.f);
    float x31 = fmaxf(a1 * inv + bb.y, 0.f);
    float p = x30 * w3.x + x31 * w3.y;
#pragma unroll
    for (int o = 16; o; o >>= 1) p += __shfl_down_sync(0xffffffffu, p, o);
    if (lane == 0) {
        g_sh3[node] = make_float2(p * as3[0], p);
        g_d3[node] = p * ad3[0];
    }
}

// ======================= Layer 3 (scalar GAT) -> output =======================
__global__ void gat_out(const float* __restrict__ b3, float* __restrict__ out, int N) {
    int node = (blockIdx.x * blockDim.x + threadIdx.x) >> 5;
    int lane = threadIdx.x & 31;
    if (node >= N) return;
    int off = g_offs[node];
    int deg = g_offs[node + 1] - off;
    float dn = g_d3[node];
    float2 self = g_sh3[node];

    float dsum = 0.f, acc = 0.f;
    for (int j = lane; j < deg; j += 32) {
        int sv = g_csr[off + j];
        float2 t = g_sh3[sv];
        float ex = exp2f(leaky(t.x + dn) * LOG2E);
        dsum += ex;
        acc += ex * t.y;
    }
#pragma unroll
    for (int o = 16; o; o >>= 1) {
        dsum += __shfl_xor_sync(0xffffffffu, dsum, o);
        acc += __shfl_xor_sync(0xffffffffu, acc, o);
    }
    if (lane == 0) {
        float exs = exp2f(leaky(self.x + dn) * LOG2E);
        out[node] = (acc + exs * self.y) / (dsum + exs) + b3[0];
    }
}

extern "C" void kernel_launch(void* const* d_in, const int* in_sizes, int n_in,
                              void* d_out, int out_size) {
    const float* x   = (const float*)d_in[0];
    const int*   ei  = (const int*)d_in[1];
    const float* W1  = (const float*)d_in[3];
    const float* as1 = (const float*)d_in[4];
    const float* ad1 = (const float*)d_in[5];
    const float* b1  = (const float*)d_in[6];
    const float* W2  = (const float*)d_in[7];
    const float* as2 = (const float*)d_in[8];
    const float* ad2 = (const float*)d_in[9];
    const float* b2  = (const float*)d_in[10];
    const float* W3  = (const float*)d_in[11];
    const float* as3 = (const float*)d_in[12];
    const float* ad3 = (const float*)d_in[13];
    const float* b3  = (const float*)d_in[14];

    int N = in_sizes[0];
    int E = in_sizes[1] / 2;
    const int* src = ei;
    const int* dst = ei + E;

    const int TB = 256;
    int gN   = (N + TB - 1) / TB;
    int gN32 = (N * 32 + TB - 1) / TB;
    int gE   = (E + TB - 1) / TB;
    int nb   = (N + 255) / 256;

    // prep + CSR build
    prep1<<<gN, TB>>>(x, W1, as1, ad1, N);
    deg_hist<<<gE, TB>>>(dst, E);
    scanA<<<nb, 256>>>(N);
    scanC<<<nb, 256>>>(N);
    scatter<<<gE, TB>>>(src, dst, E);

    // fused layers
    gat_l1_fused<<<gN32, TB>>>(W1, b1, W2, as2, ad2, N);
    gat_l2<<<gN32, TB>>>(b2, W3, as3, ad3, N);
    gat_out<<<gN32, TB>>>(b3, (float*)d_out, N);
}

// round 6
// speedup vs baseline: 2.7347x; 1.0120x over previous
#include <cuda_runtime.h>
#include <cuda_fp16.h>

#define MAXN 50176
#define MAXE 1700000
#define LOG2E 1.4426950408889634f

// Scratch (__device__ globals; no allocation allowed)
__device__ __align__(256) __half2 g_h2h[MAXN * 32];  // layer-2 features fp16 packed
__device__ __align__(16) float2 g_sx1[MAXN];         // packed (s1, x)
__device__ __align__(16) float2 g_sh3[MAXN];         // packed (s3, h3)
__device__ float g_d1[MAXN];
__device__ float g_s2[MAXN], g_d2[MAXN];
__device__ float g_d3[MAXN];
__device__ int g_deg[MAXN];          // INVARIANT: zero at kernel_launch entry (zero-init + scanA re-zeroes)
__device__ int g_offs[MAXN + 1];
__device__ int g_loc[MAXN];
__device__ int g_cursor[MAXN];
__device__ int g_csr[MAXE];
__device__ int g_bsums[256];

__device__ __forceinline__ float leaky(float v) { return v > 0.f ? v : 0.2f * v; }

// ======= merged: layer-1 rank-1 prep (first N threads) + degree histogram (E threads) =======
__global__ void prep_hist(const float* __restrict__ x, const float* __restrict__ W1,
                          const float* __restrict__ as1, const float* __restrict__ ad1,
                          const int* __restrict__ dst, int N, int E) {
    __shared__ float cs_sh, cd_sh;
    int base = blockIdx.x * blockDim.x;
    if (base < N && threadIdx.x == 0) {
        float cs = 0.f, cd = 0.f;
#pragma unroll
        for (int j = 0; j < 64; j++) { cs += W1[j] * as1[j]; cd += W1[j] * ad1[j]; }
        cs_sh = cs; cd_sh = cd;
    }
    if (base < N) __syncthreads();
    int e = base + threadIdx.x;
    if (e < E) atomicAdd(&g_deg[dst[e]], 1);
    if (e < N) {
        float xv = x[e];
        g_sx1[e] = make_float2(xv * cs_sh, xv);
        g_d1[e] = xv * cd_sh;
    }
}

// ======= scanA: 1024-thread block-local exclusive scan; re-zeroes g_deg (restores invariant) =======
__global__ void scanA(int N) {
    __shared__ int sm[1024];
    int t = threadIdx.x;
    int i = blockIdx.x * 1024 + t;
    int v = (i < N) ? g_deg[i] : 0;
    if (i < N) g_deg[i] = 0;     // restore invariant for next call
    sm[t] = v;
    __syncthreads();
#pragma unroll
    for (int o = 1; o < 1024; o <<= 1) {
        int x = (t >= o) ? sm[t - o] : 0;
        __syncthreads();
        sm[t] += x;
        __syncthreads();
    }
    if (i < N) g_loc[i] = sm[t] - v;
    if (t == 1023) g_bsums[blockIdx.x] = sm[1023];
}

// ======= scanC: block offset = sum of prior block sums (<=49), write offs/cursor =======
__global__ void scanC(int N, int E) {
    __shared__ int boff_sh;
    int b = blockIdx.x;
    if (threadIdx.x < 32) {
        int acc = 0;
        for (int j = threadIdx.x; j < b; j += 32) acc += g_bsums[j];
#pragma unroll
        for (int o = 16; o; o >>= 1) acc += __shfl_xor_sync(0xffffffffu, acc, o);
        if (threadIdx.x == 0) boff_sh = acc;
    }
    __syncthreads();
    int i = b * 1024 + threadIdx.x;
    if (i == 0) g_offs[N] = E;
    if (i >= N) return;
    int off = g_loc[i] + boff_sh;
    g_offs[i] = off;
    g_cursor[i] = off;
}

__global__ void scatter(const int* __restrict__ src, const int* __restrict__ dst, int E) {
    int e = blockIdx.x * blockDim.x + threadIdx.x;
    if (e >= E) return;
    int d = dst[e];
    int pos = atomicAdd(&g_cursor[d], 1);
    g_csr[pos] = src[e];
}

// ======= Layer 1 (scalar GAT, no max shift) + layer-2 transform (fp16 pack) =======
__global__ void gat_l1_fused(const float* __restrict__ W1, const float* __restrict__ b1,
                             const float* __restrict__ W2,
                             const float* __restrict__ as2, const float* __restrict__ ad2, int N) {
    int node = (blockIdx.x * blockDim.x + threadIdx.x) >> 5;
    int lane = threadIdx.x & 31;
    if (node >= N) return;
    int off = g_offs[node];
    int deg = g_offs[node + 1] - off;
    float dn = g_d1[node];
    float2 self = g_sx1[node];

    float dsum = 0.f, zacc = 0.f;
    for (int j = lane; j < deg; j += 32) {
        int sv = g_csr[off + j];
        float2 t = g_sx1[sv];
        float ex = exp2f(leaky(t.x + dn) * LOG2E);
        dsum += ex;
        zacc += ex * t.y;
    }
#pragma unroll
    for (int o = 16; o; o >>= 1) {
        dsum += __shfl_xor_sync(0xffffffffu, dsum, o);
        zacc += __shfl_xor_sync(0xffffffffu, zacc, o);
    }
    float exs = exp2f(leaky(self.x + dn) * LOG2E);
    float z = (zacc + exs * self.y) / (dsum + exs);

    float v0 = fmaxf(z * W1[lane] + b1[lane], 0.f);
    float v1 = fmaxf(z * W1[lane + 32] + b1[lane + 32], 0.f);
    float o0 = 0.f, o1 = 0.f;
#pragma unroll
    for (int k = 0; k < 64; k++) {
        float vk = __shfl_sync(0xffffffffu, (k < 32) ? v0 : v1, k & 31);
        float2 w = ((const float2*)W2)[k * 32 + lane];
        o0 += vk * w.x;
        o1 += vk * w.y;
    }
    g_h2h[node * 32 + lane] = __floats2half2_rn(o0, o1);
    float2 a_s = ((const float2*)as2)[lane];
    float2 a_d = ((const float2*)ad2)[lane];
    float ps = o0 * a_s.x + o1 * a_s.y;
    float pd = o0 * a_d.x + o1 * a_d.y;
#pragma unroll
    for (int o = 16; o; o >>= 1) {
        ps += __shfl_down_sync(0xffffffffu, ps, o);
        pd += __shfl_down_sync(0xffffffffu, pd, o);
    }
    if (lane == 0) { g_s2[node] = ps; g_d2[node] = pd; }
}

// ======= Layer 2 (wide GAT, fp16 gather) + layer-3 transform =======
__global__ void gat_l2(const float* __restrict__ b2, const float* __restrict__ W3,
                       const float* __restrict__ as3, const float* __restrict__ ad3, int N) {
    int node = (blockIdx.x * blockDim.x + threadIdx.x) >> 5;
    int lane = threadIdx.x & 31;
    if (node >= N) return;
    int off = g_offs[node];
    int deg = g_offs[node + 1] - off;
    float dn = g_d2[node];

    float exs = exp2f(leaky(g_s2[node] + dn) * LOG2E);
    float2 hself = __half22float2(g_h2h[node * 32 + lane]);
    float a0 = exs * hself.x;
    float a1 = exs * hself.y;
    float dsum = 0.f;
    for (int r = 0; r < deg; r += 32) {
        int j = r + lane;
        int sv = 0;
        float exv = 0.f;
        if (j < deg) {
            sv = g_csr[off + j];
            exv = exp2f(leaky(g_s2[sv] + dn) * LOG2E);
        }
        dsum += exv;
        int cnt = min(32, deg - r);
        if (cnt == 32) {
#pragma unroll 8
            for (int k = 0; k < 32; k++) {
                int sj = __shfl_sync(0xffffffffu, sv, k);
                float exj = __shfl_sync(0xffffffffu, exv, k);
                float2 hv = __half22float2(g_h2h[sj * 32 + lane]);
                a0 += exj * hv.x;
                a1 += exj * hv.y;
            }
        } else {
            for (int k = 0; k < cnt; k++) {
                int sj = __shfl_sync(0xffffffffu, sv, k);
                float exj = __shfl_sync(0xffffffffu, exv, k);
                float2 hv = __half22float2(g_h2h[sj * 32 + lane]);
                a0 += exj * hv.x;
                a1 += exj * hv.y;
            }
        }
    }
#pragma unroll
    for (int o = 16; o; o >>= 1) dsum += __shfl_xor_sync(0xffffffffu, dsum, o);
    float inv = 1.f / (exs + dsum);
    float2 bb = ((const float2*)b2)[lane];
    float2 w3 = ((const float2*)W3)[lane];
    float x30 = fmaxf(a0 * inv + bb.x, 0.f);
    float x31 = fmaxf(a1 * inv + bb.y, 0.f);
    float p = x30 * w3.x + x31 * w3.y;
#pragma unroll
    for (int o = 16; o; o >>= 1) p += __shfl_down_sync(0xffffffffu, p, o);
    if (lane == 0) {
        g_sh3[node] = make_float2(p * as3[0], p);
        g_d3[node] = p * ad3[0];
    }
}

// ======= Layer 3 (scalar GAT) -> output =======
__global__ void gat_out(const float* __restrict__ b3, float* __restrict__ out, int N) {
    int node = (blockIdx.x * blockDim.x + threadIdx.x) >> 5;
    int lane = threadIdx.x & 31;
    if (node >= N) return;
    int off = g_offs[node];
    int deg = g_offs[node + 1] - off;
    float dn = g_d3[node];
    float2 self = g_sh3[node];

    float dsum = 0.f, acc = 0.f;
    for (int j = lane; j < deg; j += 32) {
        int sv = g_csr[off + j];
        float2 t = g_sh3[sv];
        float ex = exp2f(leaky(t.x + dn) * LOG2E);
        dsum += ex;
        acc += ex * t.y;
    }
#pragma unroll
    for (int o = 16; o; o >>= 1) {
        dsum += __shfl_xor_sync(0xffffffffu, dsum, o);
        acc += __shfl_xor_sync(0xffffffffu, acc, o);
    }
    if (lane == 0) {
        float exs = exp2f(leaky(self.x + dn) * LOG2E);
        out[node] = (acc + exs * self.y) / (dsum + exs) + b3[0];
    }
}

extern "C" void kernel_launch(void* const* d_in, const int* in_sizes, int n_in,
                              void* d_out, int out_size) {
    const float* x   = (const float*)d_in[0];
    const int*   ei  = (const int*)d_in[1];
    const float* W1  = (const float*)d_in[3];
    const float* as1 = (const float*)d_in[4];
    const float* ad1 = (const float*)d_in[5];
    const float* b1  = (const float*)d_in[6];
    const float* W2  = (const float*)d_in[7];
    const float* as2 = (const float*)d_in[8];
    const float* ad2 = (const float*)d_in[9];
    const float* b2  = (const float*)d_in[10];
    const float* W3  = (const float*)d_in[11];
    const float* as3 = (const float*)d_in[12];
    const float* ad3 = (const float*)d_in[13];
    const float* b3  = (const float*)d_in[14];

    int N = in_sizes[0];
    int E = in_sizes[1] / 2;
    const int* src = ei;
    const int* dst = ei + E;

    const int TB = 256;
    int gN32 = (N * 32 + TB - 1) / TB;
    int gE   = (E + TB - 1) / TB;
    int nb   = (N + 1023) / 1024;   // 1024-thread scan blocks

    prep_hist<<<gE, TB>>>(x, W1, as1, ad1, dst, N, E);
    scanA<<<nb, 1024>>>(N);
    scanC<<<nb, 1024>>>(N, E);
    scatter<<<gE, TB>>>(src, dst, E);

    gat_l1_fused<<<gN32, TB>>>(W1, b1, W2, as2, ad2, N);
    gat_l2<<<gN32, TB>>>(b2, W3, as3, ad3, N);
    gat_out<<<gN32, TB>>>(b3, (float*)d_out, N);
}

// round 7
// speedup vs baseline: 2.7431x; 1.0031x over previous
#include <cuda_runtime.h>
#include <cuda_fp16.h>

#define MAXN 50176
#define MAXE 1700000
#define LOG2E 1.4426950408889634f

// Scratch (__device__ globals; no allocation allowed)
__device__ __align__(256) __half2 g_h2h[MAXN * 32];  // layer-2 features fp16 packed
__device__ __align__(16) float2 g_sx1[MAXN];         // packed (s1, x)
__device__ __align__(16) float2 g_sh3[MAXN];         // packed (s3, h3)
__device__ float g_d1[MAXN];
__device__ float g_s2[MAXN], g_d2[MAXN];
__device__ float g_d3[MAXN];
__device__ int g_deg[MAXN];          // INVARIANT: zero at kernel_launch entry (zero-init + scanA re-zeroes)
__device__ int g_offs[MAXN + 1];
__device__ int g_loc[MAXN];
__device__ __align__(16) int g_rank[MAXE];  // within-bucket rank per edge
__device__ int g_csr[MAXE];
__device__ int g_bsums[256];

__device__ __forceinline__ float leaky(float v) { return v > 0.f ? v : 0.2f * v; }

// ======= merged: layer-1 rank-1 prep (first N threads) + degree histogram w/ rank capture =======
// Each thread handles 4 edges (int4 loads); atomicAdd's return value = within-bucket rank.
__global__ void prep_hist(const float* __restrict__ x, const float* __restrict__ W1,
                          const float* __restrict__ as1, const float* __restrict__ ad1,
                          const int* __restrict__ dst, int N, int E) {
    __shared__ float cs_sh, cd_sh;
    int base = blockIdx.x * blockDim.x;
    if (base < N && threadIdx.x == 0) {
        float cs = 0.f, cd = 0.f;
#pragma unroll
        for (int j = 0; j < 64; j++) { cs += W1[j] * as1[j]; cd += W1[j] * ad1[j]; }
        cs_sh = cs; cd_sh = cd;
    }
    if (base < N) __syncthreads();
    int t = base + threadIdx.x;
    int e0 = t * 4;
    if (e0 + 3 < E) {
        int4 d4 = ((const int4*)dst)[t];
        int4 r4;
        r4.x = atomicAdd(&g_deg[d4.x], 1);
        r4.y = atomicAdd(&g_deg[d4.y], 1);
        r4.z = atomicAdd(&g_deg[d4.z], 1);
        r4.w = atomicAdd(&g_deg[d4.w], 1);
        ((int4*)g_rank)[t] = r4;
    } else if (e0 < E) {
        for (int e = e0; e < E; e++)
            g_rank[e] = atomicAdd(&g_deg[dst[e]], 1);
    }
    if (t < N) {
        float xv = x[t];
        g_sx1[t] = make_float2(xv * cs_sh, xv);
        g_d1[t] = xv * cd_sh;
    }
}

// ======= scanA: 1024-thread block-local exclusive scan; re-zeroes g_deg =======
__global__ void scanA(int N) {
    __shared__ int sm[1024];
    int t = threadIdx.x;
    int i = blockIdx.x * 1024 + t;
    int v = (i < N) ? g_deg[i] : 0;
    if (i < N) g_deg[i] = 0;     // restore invariant for next call
    sm[t] = v;
    __syncthreads();
#pragma unroll
    for (int o = 1; o < 1024; o <<= 1) {
        int x = (t >= o) ? sm[t - o] : 0;
        __syncthreads();
        sm[t] += x;
        __syncthreads();
    }
    if (i < N) g_loc[i] = sm[t] - v;
    if (t == 1023) g_bsums[blockIdx.x] = sm[1023];
}

// ======= scanC: block offset = sum of prior block sums (<=49), write offs =======
__global__ void scanC(int N, int E) {
    __shared__ int boff_sh;
    int b = blockIdx.x;
    if (threadIdx.x < 32) {
        int acc = 0;
        for (int j = threadIdx.x; j < b; j += 32) acc += g_bsums[j];
#pragma unroll
        for (int o = 16; o; o >>= 1) acc += __shfl_xor_sync(0xffffffffu, acc, o);
        if (threadIdx.x == 0) boff_sh = acc;
    }
    __syncthreads();
    int i = b * 1024 + threadIdx.x;
    if (i == 0) g_offs[N] = E;
    if (i >= N) return;
    g_offs[i] = g_loc[i] + boff_sh;
}

// ======= scatter: atomic-free (uses precomputed rank); 4 edges/thread =======
__global__ void scatter(const int* __restrict__ src, const int* __restrict__ dst, int E) {
    int t = blockIdx.x * blockDim.x + threadIdx.x;
    int e0 = t * 4;
    if (e0 + 3 < E) {
        int4 s4 = ((const int4*)src)[t];
        int4 d4 = ((const int4*)dst)[t];
        int4 r4 = ((const int4*)g_rank)[t];
        int o0 = g_offs[d4.x], o1 = g_offs[d4.y], o2 = g_offs[d4.z], o3 = g_offs[d4.w];
        g_csr[o0 + r4.x] = s4.x;
        g_csr[o1 + r4.y] = s4.y;
        g_csr[o2 + r4.z] = s4.z;
        g_csr[o3 + r4.w] = s4.w;
    } else if (e0 < E) {
        for (int e = e0; e < E; e++)
            g_csr[g_offs[dst[e]] + g_rank[e]] = src[e];
    }
}

// ======= Layer 1 (scalar GAT, no max shift) + layer-2 transform (fp16 pack) =======
__global__ void gat_l1_fused(const float* __restrict__ W1, const float* __restrict__ b1,
                             const float* __restrict__ W2,
                             const float* __restrict__ as2, const float* __restrict__ ad2, int N) {
    int node = (blockIdx.x * blockDim.x + threadIdx.x) >> 5;
    int lane = threadIdx.x & 31;
    if (node >= N) return;
    int off = g_offs[node];
    int deg = g_offs[node + 1] - off;
    float dn = g_d1[node];
    float2 self = g_sx1[node];

    float dsum = 0.f, zacc = 0.f;
    for (int j = lane; j < deg; j += 32) {
        int sv = g_csr[off + j];
        float2 t = g_sx1[sv];
        float ex = exp2f(leaky(t.x + dn) * LOG2E);
        dsum += ex;
        zacc += ex * t.y;
    }
#pragma unroll
    for (int o = 16; o; o >>= 1) {
        dsum += __shfl_xor_sync(0xffffffffu, dsum, o);
        zacc += __shfl_xor_sync(0xffffffffu, zacc, o);
    }
    float exs = exp2f(leaky(self.x + dn) * LOG2E);
    float z = (zacc + exs * self.y) / (dsum + exs);

    float v0 = fmaxf(z * W1[lane] + b1[lane], 0.f);
    float v1 = fmaxf(z * W1[lane + 32] + b1[lane + 32], 0.f);
    float o0 = 0.f, o1 = 0.f;
#pragma unroll
    for (int k = 0; k < 64; k++) {
        float vk = __shfl_sync(0xffffffffu, (k < 32) ? v0 : v1, k & 31);
        float2 w = ((const float2*)W2)[k * 32 + lane];
        o0 += vk * w.x;
        o1 += vk * w.y;
    }
    g_h2h[node * 32 + lane] = __floats2half2_rn(o0, o1);
    float2 a_s = ((const float2*)as2)[lane];
    float2 a_d = ((const float2*)ad2)[lane];
    float ps = o0 * a_s.x + o1 * a_s.y;
    float pd = o0 * a_d.x + o1 * a_d.y;
#pragma unroll
    for (int o = 16; o; o >>= 1) {
        ps += __shfl_down_sync(0xffffffffu, ps, o);
        pd += __shfl_down_sync(0xffffffffu, pd, o);
    }
    if (lane == 0) { g_s2[node] = ps; g_d2[node] = pd; }
}

// ======= Layer 2 (wide GAT, fp16 gather) + layer-3 transform =======
__global__ void gat_l2(const float* __restrict__ b2, const float* __restrict__ W3,
                       const float* __restrict__ as3, const float* __restrict__ ad3, int N) {
    int node = (blockIdx.x * blockDim.x + threadIdx.x) >> 5;
    int lane = threadIdx.x & 31;
    if (node >= N) return;
    int off = g_offs[node];
    int deg = g_offs[node + 1] - off;
    float dn = g_d2[node];

    float exs = exp2f(leaky(g_s2[node] + dn) * LOG2E);
    float2 hself = __half22float2(g_h2h[node * 32 + lane]);
    float a0 = exs * hself.x;
    float a1 = exs * hself.y;
    float dsum = 0.f;
    for (int r = 0; r < deg; r += 32) {
        int j = r + lane;
        int sv = 0;
        float exv = 0.f;
        if (j < deg) {
            sv = g_csr[off + j];
            exv = exp2f(leaky(g_s2[sv] + dn) * LOG2E);
        }
        dsum += exv;
        int cnt = min(32, deg - r);
        if (cnt == 32) {
#pragma unroll 8
            for (int k = 0; k < 32; k++) {
                int sj = __shfl_sync(0xffffffffu, sv, k);
                float exj = __shfl_sync(0xffffffffu, exv, k);
                float2 hv = __half22float2(g_h2h[sj * 32 + lane]);
                a0 += exj * hv.x;
                a1 += exj * hv.y;
            }
        } else {
            for (int k = 0; k < cnt; k++) {
                int sj = __shfl_sync(0xffffffffu, sv, k);
                float exj = __shfl_sync(0xffffffffu, exv, k);
                float2 hv = __half22float2(g_h2h[sj * 32 + lane]);
                a0 += exj * hv.x;
                a1 += exj * hv.y;
            }
        }
    }
#pragma unroll
    for (int o = 16; o; o >>= 1) dsum += __shfl_xor_sync(0xffffffffu, dsum, o);
    float inv = 1.f / (exs + dsum);
    float2 bb = ((const float2*)b2)[lane];
    float2 w3 = ((const float2*)W3)[lane];
    float x30 = fmaxf(a0 * inv + bb.x, 0.f);
    float x31 = fmaxf(a1 * inv + bb.y, 0.f);
    float p = x30 * w3.x + x31 * w3.y;
#pragma unroll
    for (int o = 16; o; o >>= 1) p += __shfl_down_sync(0xffffffffu, p, o);
    if (lane == 0) {
        g_sh3[node] = make_float2(p * as3[0], p);
        g_d3[node] = p * ad3[0];
    }
}

// ======= Layer 3 (scalar GAT) -> output =======
__global__ void gat_out(const float* __restrict__ b3, float* __restrict__ out, int N) {
    int node = (blockIdx.x * blockDim.x + threadIdx.x) >> 5;
    int lane = threadIdx.x & 31;
    if (node >= N) return;
    int off = g_offs[node];
    int deg = g_offs[node + 1] - off;
    float dn = g_d3[node];
    float2 self = g_sh3[node];

    float dsum = 0.f, acc = 0.f;
    for (int j = lane; j < deg; j += 32) {
        int sv = g_csr[off + j];
        float2 t = g_sh3[sv];
        float ex = exp2f(leaky(t.x + dn) * LOG2E);
        dsum += ex;
        acc += ex * t.y;
    }
#pragma unroll
    for (int o = 16; o; o >>= 1) {
        dsum += __shfl_xor_sync(0xffffffffu, dsum, o);
        acc += __shfl_xor_sync(0xffffffffu, acc, o);
    }
    if (lane == 0) {
        float exs = exp2f(leaky(self.x + dn) * LOG2E);
        out[node] = (acc + exs * self.y) / (dsum + exs) + b3[0];
    }
}

extern "C" void kernel_launch(void* const* d_in, const int* in_sizes, int n_in,
                              void* d_out, int out_size) {
    const float* x   = (const float*)d_in[0];
    const int*   ei  = (const int*)d_in[1];
    const float* W1  = (const float*)d_in[3];
    const float* as1 = (const float*)d_in[4];
    const float* ad1 = (const float*)d_in[5];
    const float* b1  = (const float*)d_in[6];
    const float* W2  = (const float*)d_in[7];
    const float* as2 = (const float*)d_in[8];
    const float* ad2 = (const float*)d_in[9];
    const float* b2  = (const float*)d_in[10];
    const float* W3  = (const float*)d_in[11];
    const float* as3 = (const float*)d_in[12];
    const float* ad3 = (const float*)d_in[13];
    const float* b3  = (const float*)d_in[14];

    int N = in_sizes[0];
    int E = in_sizes[1] / 2;
    const int* src = ei;
    const int* dst = ei + E;

    const int TB = 256;
    int gN32 = (N * 32 + TB - 1) / TB;
    int e4   = (E + 3) / 4;                 // threads for 4-edge-per-thread kernels
    int gPH  = (((e4 > N) ? e4 : N) + TB - 1) / TB;
    int gSC  = (e4 + TB - 1) / TB;
    int nb   = (N + 1023) / 1024;

    prep_hist<<<gPH, TB>>>(x, W1, as1, ad1, dst, N, E);
    scanA<<<nb, 1024>>>(N);
    scanC<<<nb, 1024>>>(N, E);
    scatter<<<gSC, TB>>>(src, dst, E);

    gat_l1_fused<<<gN32, TB>>>(W1, b1, W2, as2, ad2, N);
    gat_l2<<<gN32, TB>>>(b2, W3, as3, ad3, N);
    gat_out<<<gN32, TB>>>(b3, (float*)d_out, N);
}